// round 17
// baseline (speedup 1.0000x reference)
#include <cuda_runtime.h>
#include <cuda_bf16.h>

#define VSA_N     2048
#define VSA_BLK   512           // 16 warps
#define VSA_ROWS  16            // rows per block; lane l -> row (l & 15)
#define VSA_PAIRS 1024          // j-pairs per batch
// 32 streams per block (warp*2 + half-warp), 32 j-pairs per stream.

typedef unsigned long long ull;

#define F32X2_MUL(d, a, b) \
    asm("mul.rn.f32x2 %0, %1, %2;" : "=l"(d) : "l"(a), "l"(b))
#define F32X2_ADD(d, a, b) \
    asm("add.rn.f32x2 %0, %1, %2;" : "=l"(d) : "l"(a), "l"(b))
#define F32X2_FMA(d, a, b, c) \
    asm("fma.rn.f32x2 %0, %1, %2, %3;" : "=l"(d) : "l"(a), "l"(b), "l"(c))
#define F32X2_PACK(d, lo, hi) \
    asm("mov.b64 %0, {%1, %2};" : "=l"(d) : "f"(lo), "f"(hi))
#define F32X2_UNPACK(lo, hi, s) \
    asm("mov.b64 {%0, %1}, %2;" : "=f"(lo), "=f"(hi) : "l"(s))

// ---------------------------------------------------------------------------
// PACKED f32x2 hot loop x FULL warp supply (the untested combination):
//   R13 showed packed math matches the scalar plateau at HALF the warps;
//   R14 layout supplies 8192 warps. grid = (128, B) = 512 blocks x 16 warps.
//   * lane l owns row i = bx*16 + (l & 15)
//   * stream s = warp*2 + (l>>4) walks j-pairs [s*32, s*32+32)
//   * tile pair-interleaved per pair p: [x0,x1,y0,y1 | z0,z1,kk0,kk1]
//     -> two LDS.128 give four f32x2 operands with zero pack movs
//     (UNPADDED: R16 proved the padding "fix" regresses).
//
// Math (validated since R6/R12): T_i = q_i x (sum_j e_ij k_j),
// |q x k|^2 = |q|^2|k|^2 - (q.k)^2, k' = (k-mk)*log2e/sqrt(N),
// e = ex2(sqrt(|n2'|)). Sign/abs handled by 64-bit immediate LOP ops
// (zero mask registers). Register budget fought down for the (512,4)
// 32-reg cap: q packs 8 + accums 8 + ptr/loop 2 persistent.
// ---------------------------------------------------------------------------
__global__ __launch_bounds__(VSA_BLK, 4)
void vsa_fused_kernel(const float* __restrict__ q,
                      const float* __restrict__ k,
                      const float* __restrict__ v,
                      float* __restrict__ out) {
    __shared__ double2 sk2[VSA_PAIRS * 2];   // 32 KB; reused for partials
    __shared__ float   red[VSA_BLK / 32][9];
    __shared__ float   means[9];

    const int tid  = threadIdx.x;
    const int b    = blockIdx.y;
    const int warp = tid >> 5;
    const int lane = tid & 31;

    const float* qb = q + (size_t)b * VSA_N * 3;
    const float* kb = k + (size_t)b * VSA_N * 3;
    const float* vb = v + (size_t)b * VSA_N * 3;

    // ---- Phase A: per-batch means (scalar, exactly as the 19.6us R14) ----
    {
        float s[9];
#pragma unroll
        for (int c = 0; c < 9; c++) s[c] = 0.0f;

#pragma unroll
        for (int r = 0; r < VSA_N / VSA_BLK; r++) {
            const int o = (tid + r * VSA_BLK) * 3;
            s[0] += qb[o + 0]; s[1] += qb[o + 1]; s[2] += qb[o + 2];
            s[3] += kb[o + 0]; s[4] += kb[o + 1]; s[5] += kb[o + 2];
            s[6] += vb[o + 0]; s[7] += vb[o + 1]; s[8] += vb[o + 2];
        }
#pragma unroll
        for (int c = 0; c < 9; c++) {
#pragma unroll
            for (int off = 16; off > 0; off >>= 1)
                s[c] += __shfl_xor_sync(0xFFFFFFFFu, s[c], off);
        }
        if (lane == 0) {
#pragma unroll
            for (int c = 0; c < 9; c++) red[warp][c] = s[c];
        }
        __syncthreads();
        if (tid < 9) {
            float t = 0.0f;
#pragma unroll
            for (int w = 0; w < VSA_BLK / 32; w++) t += red[w][tid];
            means[tid] = t * (1.0f / (float)VSA_N);
        }
        __syncthreads();
    }

    const float mqx = means[0], mqy = means[1], mqz = means[2];
    const float mkx = means[3], mky = means[4], mkz = means[5];
    const float mvx = means[6], mvy = means[7], mvz = means[8];

    // c1 = log2(e) / sqrt(2048)   (ex2 path)
    const float c1 = 1.4426950408889634f * 0.022097086912079612f;

    // ---- Phase B: stage k' pair-interleaved (2 pairs per thread) ----
    {
        float* skf = (float*)sk2;
#pragma unroll
        for (int r = 0; r < 2; r++) {
            const int p = tid + r * VSA_BLK;   // pair index 0..1023
            const int j0 = 2 * p, j1 = 2 * p + 1;
            const float x0 = (kb[j0 * 3 + 0] - mkx) * c1;
            const float y0 = (kb[j0 * 3 + 1] - mky) * c1;
            const float z0 = (kb[j0 * 3 + 2] - mkz) * c1;
            const float x1 = (kb[j1 * 3 + 0] - mkx) * c1;
            const float y1 = (kb[j1 * 3 + 1] - mky) * c1;
            const float z1 = (kb[j1 * 3 + 2] - mkz) * c1;
            const int base = p * 8;
            skf[base + 0] = x0;
            skf[base + 1] = x1;
            skf[base + 2] = y0;
            skf[base + 3] = y1;
            skf[base + 4] = z0;
            skf[base + 5] = z1;
            skf[base + 6] = fmaf(x0, x0, fmaf(y0, y0, z0 * z0));
            skf[base + 7] = fmaf(x1, x1, fmaf(y1, y1, z1 * z1));
        }
    }
    __syncthreads();

    // ---- Phase C: packed hot loop ----
    const int row    = lane & 15;
    const int stream = warp * 2 + (lane >> 4);   // 0..31
    const int i      = blockIdx.x * VSA_ROWS + row;

    ull qx2, qy2, qz2, qq2;
    {
        const float qx = qb[i * 3 + 0] - mqx;
        const float qy = qb[i * 3 + 1] - mqy;
        const float qz = qb[i * 3 + 2] - mqz;
        const float qq = fmaf(qx, qx, fmaf(qy, qy, qz * qz));
        F32X2_PACK(qx2, qx, qx);
        F32X2_PACK(qy2, qy, qy);
        F32X2_PACK(qz2, qz, qz);
        F32X2_PACK(qq2, qq, qq);
    }

    ull Z2 = 0ull, Wx2 = 0ull, Wy2 = 0ull, Wz2 = 0ull;

    const double2* p2 = sk2 + stream * 64;   // 32 pairs * 2 double2
#pragma unroll 2
    for (int t = 0; t < 32; t++) {
        const double2 d0 = p2[2 * t + 0];    // (x0,x1)(y0,y1)
        const double2 d1 = p2[2 * t + 1];    // (z0,z1)(kk0,kk1)
        const ull kx2 = (ull)__double_as_longlong(d0.x);
        const ull ky2 = (ull)__double_as_longlong(d0.y);
        const ull kz2 = (ull)__double_as_longlong(d1.x);
        const ull kk2 = (ull)__double_as_longlong(d1.y);

        ull dot2, n2;
        F32X2_MUL(dot2, qx2, kx2);
        F32X2_FMA(dot2, qy2, ky2, dot2);
        F32X2_FMA(dot2, qz2, kz2, dot2);
        F32X2_MUL(n2, dot2, dot2);
        // n2 = qq*kk - dot^2, via 64-bit immediate xor (no mask registers)
        asm("xor.b64 %0, %0, 0x8000000080000000;" : "+l"(n2));
        F32X2_FMA(n2, qq2, kk2, n2);
        asm("and.b64 %0, %0, 0x7FFFFFFF7FFFFFFF;" : "+l"(n2));  // |n2|

        float na, nb, ea, eb;
        F32X2_UNPACK(na, nb, n2);
        asm("sqrt.approx.f32 %0, %1;" : "=f"(ea) : "f"(na));
        asm("sqrt.approx.f32 %0, %1;" : "=f"(eb) : "f"(nb));
        asm("ex2.approx.f32 %0, %1;"  : "=f"(ea) : "f"(ea));
        asm("ex2.approx.f32 %0, %1;"  : "=f"(eb) : "f"(eb));

        ull e2;
        F32X2_PACK(e2, ea, eb);
        F32X2_ADD(Z2, Z2, e2);
        F32X2_FMA(Wx2, e2, kx2, Wx2);
        F32X2_FMA(Wy2, e2, ky2, Wy2);
        F32X2_FMA(Wz2, e2, kz2, Wz2);
    }

    // Collapse packed halves.
    float Z, Wx, Wy, Wz;
    {
        float a0, a1;
        F32X2_UNPACK(a0, a1, Z2);  Z  = a0 + a1;
        F32X2_UNPACK(a0, a1, Wx2); Wx = a0 + a1;
        F32X2_UNPACK(a0, a1, Wy2); Wy = a0 + a1;
        F32X2_UNPACK(a0, a1, Wz2); Wz = a0 + a1;
    }

    // ---- Phase D: reduce 32 stream-partials per row (as R14) ----
    __syncthreads();   // all warps done reading sk2
    float4* part = (float4*)sk2;             // part[stream*17 + row]
    part[stream * 17 + row] = make_float4(Z, Wx, Wy, Wz);
    __syncthreads();

    if (warp < VSA_ROWS) {
        const float4 p = part[lane * 17 + warp];
        float Zr = p.x, Wxr = p.y, Wyr = p.z, Wzr = p.w;
#pragma unroll
        for (int off = 16; off > 0; off >>= 1) {
            Zr  += __shfl_xor_sync(0xFFFFFFFFu, Zr,  off);
            Wxr += __shfl_xor_sync(0xFFFFFFFFu, Wxr, off);
            Wyr += __shfl_xor_sync(0xFFFFFFFFu, Wyr, off);
            Wzr += __shfl_xor_sync(0xFFFFFFFFu, Wzr, off);
        }

        if (lane == 0) {
            const int ir = blockIdx.x * VSA_ROWS + warp;
            const float qxr = qb[ir * 3 + 0] - mqx;
            const float qyr = qb[ir * 3 + 1] - mqy;
            const float qzr = qb[ir * 3 + 2] - mqz;
            // T' = q x W (= c1 * T);  u = cross(T, v_c) / (Z * N)
            const float Tx = fmaf(qyr, Wzr, -qzr * Wyr);
            const float Ty = fmaf(qzr, Wxr, -qxr * Wzr);
            const float Tz = fmaf(qxr, Wyr, -qyr * Wxr);
            const float vx = vb[ir * 3 + 0] - mvx;
            const float vy = vb[ir * 3 + 1] - mvy;
            const float vz = vb[ir * 3 + 2] - mvz;
            const float inv = 1.0f / (Zr * (float)VSA_N * c1);
            float* o = out + ((size_t)b * VSA_N + ir) * 3;
            o[0] = fmaf(Ty, vz, -Tz * vy) * inv;
            o[1] = fmaf(Tz, vx, -Tx * vz) * inv;
            o[2] = fmaf(Tx, vy, -Ty * vx) * inv;
        }
    }
}

// ---------------------------------------------------------------------------
extern "C" void kernel_launch(void* const* d_in, const int* in_sizes, int n_in,
                              void* d_out, int out_size) {
    const float* q = (const float*)d_in[0];
    const float* k = (const float*)d_in[1];
    const float* v = (const float*)d_in[2];
    float* out = (float*)d_out;

    const int B = out_size / (VSA_N * 3);   // = 4

    dim3 grid(VSA_N / VSA_ROWS, B);         // (128, 4) = 512 blocks
    vsa_fused_kernel<<<grid, VSA_BLK>>>(q, k, v, out);
}